// round 10
// baseline (speedup 1.0000x reference)
#include <cuda_runtime.h>
#include <cuda_bf16.h>
#include <cstdint>

#define NN 100000
#define EE 1600000
#define FF 128
#define NG 512
#define LL 3
#define BN_EPS 1e-5f
#define TILES 782              // ceil(NN/128)

#if defined(__CUDA_ARCH__) && defined(__CUDA_ARCH_FEAT_SM103_ALL)
#define HAS_TC 1
#else
#define HAS_TC 0
#endif

// ---------------- scratch (device globals; no allocation allowed) ----------
__device__ float g_q[NN * FF];
__device__ int   g_deg[NN];
__device__ int   g_off[NN + 1];
__device__ int   g_cur[NN];
__device__ int   g_srcs[EE];
__device__ float g_stats[2 * FF];
__device__ float g_sc[FF];
__device__ float g_sh[FF];
// Split-bf16 activations, 32KB per 128-row tile.
//  - tcgen05 path: blocked-atom SW128 (blk_off)   - fallback: row-major
// Tail rows (>= NN) stay zero (zero-init globals, never written).
__device__ uint4 g_Ahi[TILES * 2048];
__device__ uint4 g_Alo[TILES * 2048];
__device__ uint4 g_Bhi[6 * 2048];
__device__ uint4 g_Blo[6 * 2048];

__device__ __forceinline__ uint32_t blk_off(int r, int k) {
    uint32_t b = (uint32_t)(((r >> 3) + (k >> 6) * 16) * 1024 + (r & 7) * 128 + (k & 63) * 2);
    return b ^ ((b >> 3) & 0x70);
}
__device__ __forceinline__ unsigned short bf_hi(float v, float& rem) {
    __nv_bfloat16 h = __float2bfloat16_rn(v);
    rem = v - __bfloat162float(h);
    return __bfloat16_as_ushort(h);
}
__device__ __forceinline__ unsigned short bf_rn(float v) {
    return __bfloat16_as_ushort(__float2bfloat16_rn(v));
}

#if HAS_TC
// ---------------- tcgen05 helpers (sm_103a only) ---------------------------
__device__ __forceinline__ uint32_t elect_one_pred() {
    uint32_t pred;
    asm volatile(
        "{\n\t.reg .pred p;\n\telect.sync _|p, 0xFFFFFFFF;\n\tselp.b32 %0, 1, 0, p;\n\t}"
        : "=r"(pred));
    return pred;
}
#define TCGEN05_ALLOC(sa, n) \
    asm volatile("tcgen05.alloc.cta_group::1.sync.aligned.shared::cta.b32 [%0], %1;" \
                 :: "r"((uint32_t)(sa)), "r"((uint32_t)(n)) : "memory")
#define TCGEN05_DEALLOC(t, n) \
    asm volatile("tcgen05.dealloc.cta_group::1.sync.aligned.b32 %0, %1;" :: "r"(t), "r"(n))
#define TCGEN05_RELINQ() \
    asm volatile("tcgen05.relinquish_alloc_permit.cta_group::1.sync.aligned;")
#define TCGEN05_COMMIT(mb) \
    asm volatile("tcgen05.commit.cta_group::1.mbarrier::arrive::one.shared::cluster.b64 [%0];" \
                 :: "r"((uint32_t)(mb)) : "memory")
#define TCGEN05_WAIT_LD()  asm volatile("tcgen05.wait::ld.sync.aligned;" ::: "memory")
#define TCGEN05_FENCE_BEFORE() asm volatile("tcgen05.fence::before_thread_sync;" ::: "memory")
#define TCGEN05_FENCE_AFTER()  asm volatile("tcgen05.fence::after_thread_sync;" ::: "memory")
#define TCGEN05_LD_X32(r, ta) \
    asm volatile( \
        "tcgen05.ld.sync.aligned.32x32b.x32.b32 " \
        "{%0, %1, %2, %3, %4, %5, %6, %7, " \
        " %8, %9, %10, %11, %12, %13, %14, %15, " \
        " %16, %17, %18, %19, %20, %21, %22, %23, " \
        " %24, %25, %26, %27, %28, %29, %30, %31}, [%32];" \
        : "=r"((r)[0]),  "=r"((r)[1]),  "=r"((r)[2]),  "=r"((r)[3]), \
          "=r"((r)[4]),  "=r"((r)[5]),  "=r"((r)[6]),  "=r"((r)[7]), \
          "=r"((r)[8]),  "=r"((r)[9]),  "=r"((r)[10]), "=r"((r)[11]), \
          "=r"((r)[12]), "=r"((r)[13]), "=r"((r)[14]), "=r"((r)[15]), \
          "=r"((r)[16]), "=r"((r)[17]), "=r"((r)[18]), "=r"((r)[19]), \
          "=r"((r)[20]), "=r"((r)[21]), "=r"((r)[22]), "=r"((r)[23]), \
          "=r"((r)[24]), "=r"((r)[25]), "=r"((r)[26]), "=r"((r)[27]), \
          "=r"((r)[28]), "=r"((r)[29]), "=r"((r)[30]), "=r"((r)[31]) \
        : "r"(ta))

static constexpr uint64_t SMEM_DESC_BASE_SW128 =
    (uint64_t(2) << 61) | (uint64_t(1) << 46) | (uint64_t(64) << 32) | (uint64_t(1) << 16);
#define MAKE_SMEM_DESC(ba) (SMEM_DESC_BASE_SW128 | ((uint64_t)((ba) >> 4) & 0x3FFF))

__device__ __forceinline__ void mma_f16_ss(uint32_t d, uint64_t a, uint64_t b,
                                           uint32_t idesc, uint32_t en) {
    asm volatile(
        "{\n\t.reg .pred p;\n\tsetp.ne.u32 p, %5, 0;\n\t"
        "tcgen05.mma.cta_group::1.kind::f16 [%0], %1, %2, %3, {%4, %4, %4, %4}, p;\n\t}"
        :: "r"(d), "l"(a), "l"(b), "r"(idesc), "r"(0u), "r"(en) : "memory");
}
// idesc: dtype F32, atype/btype BF16, N=128, M=128
#define MMA_IDESC 0x8200490u

__device__ __forceinline__ uint32_t smem_to_u32(const void* p) {
    uint32_t a;
    asm("{ .reg .u64 t; cvta.to.shared.u64 t, %1; cvt.u32.u64 %0, t; }" : "=r"(a) : "l"(p));
    return a;
}
#define MBARRIER_INIT(mb, c) \
    asm volatile("mbarrier.init.shared.b64 [%0], %1;" :: "r"((uint32_t)(mb)), "r"((uint32_t)(c)) : "memory")
__device__ __forceinline__ void mbar_inval(uint32_t mb) {
    asm volatile("mbarrier.inval.shared.b64 [%0];" :: "r"(mb) : "memory");
}
#define MBARRIER_WAIT_PARITY(mb, ph) do {                                      \
    uint32_t _mb = (uint32_t)(mb); uint32_t _p = (uint32_t)(ph); uint32_t _d;  \
    asm volatile("{\n\t.reg .pred p;\n\t"                                      \
        "mbarrier.try_wait.parity.acquire.cta.shared::cta.b64 p, [%1], %2;\n\t"\
        "selp.b32 %0, 1, 0, p;\n\t}" : "=r"(_d) : "r"(_mb), "r"(_p) : "memory");\
    if (!_d) {                                                                 \
        asm volatile("{\n\t.reg .pred P1;\n\t"                                 \
            "WL_%=:\n\t"                                                       \
            "mbarrier.try_wait.parity.acquire.cta.shared::cta.b64 P1, [%0], %1, 0x989680;\n\t" \
            "@P1 bra.uni WD_%=;\n\tbra.uni WL_%=;\n\tWD_%=:\n\t}"              \
            :: "r"(_mb), "r"(_p) : "memory");                                  \
    } } while (0)
#define FENCE_PROXY_ASYNC() asm volatile("fence.proxy.async.shared::cta;" ::: "memory")
#else
#define MMA_BF16(C, A, B0, B1)                                                 \
    asm volatile(                                                              \
        "mma.sync.aligned.m16n8k16.row.col.f32.bf16.bf16.f32 "                 \
        "{%0,%1,%2,%3}, {%4,%5,%6,%7}, {%8,%9}, {%0,%1,%2,%3};"                \
        : "+f"((C)[0]), "+f"((C)[1]), "+f"((C)[2]), "+f"((C)[3])               \
        : "r"((A)[0]), "r"((A)[1]), "r"((A)[2]), "r"((A)[3]),                  \
          "r"(B0), "r"(B1))
#endif

// ---------------- CSR build (4-edge ILP) ------------------------------------
__global__ void hist_k(const int* __restrict__ dst) {
    int base = blockIdx.x * 1024 + threadIdx.x;
#pragma unroll
    for (int i = 0; i < 4; i++) {
        int e = base + i * 256;
        if (e < EE) atomicAdd(&g_deg[dst[e]], 1);
    }
}

__global__ void scan_k() {
    const int T = 1024;
    int tid = threadIdx.x;
    int per = (NN + T - 1) / T;
    int start = min(tid * per, NN), end = min(start + per, NN);
    int s = 0;
    for (int i = start; i < end; i++) s += g_deg[i];
    int lane = tid & 31, w = tid >> 5;
    int v = s;
#pragma unroll
    for (int o = 1; o < 32; o <<= 1) {
        int t = __shfl_up_sync(0xffffffffu, v, o);
        if (lane >= o) v += t;
    }
    __shared__ int wsum[32];
    if (lane == 31) wsum[w] = v;
    __syncthreads();
    if (w == 0) {
        int x = wsum[lane];
#pragma unroll
        for (int o = 1; o < 32; o <<= 1) {
            int t = __shfl_up_sync(0xffffffffu, x, o);
            if (lane >= o) x += t;
        }
        wsum[lane] = x;
    }
    __syncthreads();
    int excl = v - s + (w > 0 ? wsum[w - 1] : 0);
    int run = excl;
    for (int i = start; i < end; i++) {
        int c = g_deg[i];
        g_off[i] = run;
        g_cur[i] = run;
        run += c;
    }
    if (tid == T - 1) g_off[NN] = run;
}

__global__ void scatter_k(const int* __restrict__ src, const int* __restrict__ dst) {
    int base = blockIdx.x * 1024 + threadIdx.x;
#pragma unroll
    for (int i = 0; i < 4; i++) {
        int e = base + i * 256;
        if (e < EE) {
            int d = dst[e];
            int p = atomicAdd(&g_cur[d], 1);
            g_srcs[p] = src[e];
        }
    }
}

// ---------------- weight prep: Wt[n][k]=W[k][n], split bf16 ---------------
__global__ void prep_w(const float* __restrict__ W1, const float* __restrict__ W2) {
    int b = blockIdx.x;
    int layer = b >> 1;
    const float* W = ((b & 1) ? W2 : W1) + layer * FF * FF;
    uint8_t* dh = (uint8_t*)g_Bhi + b * 32768;
    uint8_t* dl = (uint8_t*)g_Blo + b * 32768;
    int n = threadIdx.x;
    for (int k = 0; k < FF; k++) {
        float w = W[k * FF + n];
        float rem;
        unsigned short h = bf_hi(w, rem);
        unsigned short l = bf_rn(rem);
#if HAS_TC
        uint32_t off = blk_off(n, k);
#else
        uint32_t off = (uint32_t)(n * 128 + k) * 2;
#endif
        *(unsigned short*)(dh + off) = h;
        *(unsigned short*)(dl + off) = l;
    }
}

// ------ aggregation with fused BN affine, x4-unrolled gather ---------------
__global__ void agg_k(const float* __restrict__ h, int affine) {
    int gw = (blockIdx.x * blockDim.x + threadIdx.x) >> 5;
    int lane = threadIdx.x & 31;
    if (gw >= NN) return;
    const float4* h4 = (const float4*)h;
    float4 a0 = h4[gw * 32 + lane];
    float4 a1 = make_float4(0.f, 0.f, 0.f, 0.f);
    float4 a2 = make_float4(0.f, 0.f, 0.f, 0.f);
    float4 a3 = make_float4(0.f, 0.f, 0.f, 0.f);
    int s0 = g_off[gw], s1 = g_off[gw + 1];
    int e = s0;
    for (; e + 4 <= s1; e += 4) {
        int i0 = g_srcs[e], i1 = g_srcs[e + 1], i2 = g_srcs[e + 2], i3 = g_srcs[e + 3];
        float4 v0 = __ldg(&h4[i0 * 32 + lane]);
        float4 v1 = __ldg(&h4[i1 * 32 + lane]);
        float4 v2 = __ldg(&h4[i2 * 32 + lane]);
        float4 v3 = __ldg(&h4[i3 * 32 + lane]);
        a0.x += v0.x; a0.y += v0.y; a0.z += v0.z; a0.w += v0.w;
        a1.x += v1.x; a1.y += v1.y; a1.z += v1.z; a1.w += v1.w;
        a2.x += v2.x; a2.y += v2.y; a2.z += v2.z; a2.w += v2.w;
        a3.x += v3.x; a3.y += v3.y; a3.z += v3.z; a3.w += v3.w;
    }
    for (; e < s1; e++) {
        int s = g_srcs[e];
        float4 v = __ldg(&h4[s * 32 + lane]);
        a0.x += v.x; a0.y += v.y; a0.z += v.z; a0.w += v.w;
    }
    float4 acc;
    acc.x = (a0.x + a1.x) + (a2.x + a3.x);
    acc.y = (a0.y + a1.y) + (a2.y + a3.y);
    acc.z = (a0.z + a1.z) + (a2.z + a3.z);
    acc.w = (a0.w + a1.w) + (a2.w + a3.w);
    if (affine) {
        float4 sc4 = ((const float4*)g_sc)[lane];
        float4 sh4 = ((const float4*)g_sh)[lane];
        float cnt = (float)(s1 - s0 + 1);
        acc.x = fmaf(sc4.x, acc.x, cnt * sh4.x);
        acc.y = fmaf(sc4.y, acc.y, cnt * sh4.y);
        acc.z = fmaf(sc4.z, acc.z, cnt * sh4.z);
        acc.w = fmaf(sc4.w, acc.w, cnt * sh4.w);
    }
    float r0, r1, r2, r3;
    unsigned short h0 = bf_hi(acc.x, r0), h1 = bf_hi(acc.y, r1);
    unsigned short h2 = bf_hi(acc.z, r2), h3 = bf_hi(acc.w, r3);
    uint2 hv = make_uint2((uint32_t)h0 | ((uint32_t)h1 << 16),
                          (uint32_t)h2 | ((uint32_t)h3 << 16));
    uint2 lv = make_uint2((uint32_t)bf_rn(r0) | ((uint32_t)bf_rn(r1) << 16),
                          (uint32_t)bf_rn(r2) | ((uint32_t)bf_rn(r3) << 16));
#if HAS_TC
    int tile = gw >> 7, r = gw & 127;
    uint32_t off = blk_off(r, lane * 4);
    *(uint2*)((uint8_t*)g_Ahi + tile * 32768 + off) = hv;
    *(uint2*)((uint8_t*)g_Alo + tile * 32768 + off) = lv;
#else
    ((uint2*)g_Ahi)[gw * 32 + lane] = hv;
    ((uint2*)g_Alo)[gw * 32 + lane] = lv;
#endif
}

// ---------------- fused MLP (EXACT R6 body, known-passing) -----------------
// TC layout:
#define TC_TMEMPTR 0
#define TC_MBAR    8
#define TC_BS1     64
#define TC_BS2     576
#define TC_AHI     2048
#define TC_ALO     (TC_AHI + 32768)
#define TC_B1HI    (TC_ALO + 32768)
#define TC_B1LO    (TC_B1HI + 32768)
#define TC_B2HI    (TC_B1LO + 32768)
#define TC_B2LO    (TC_B2HI + 32768)
#define TC_QS      TC_AHI                  // reuse after MMA2 (needs 66048B)
#define TC_TOTAL   (TC_B2LO + 32768)       // 198656
// fallback layout: rows padded to 272B
#define SROW 272
#define BUFB (128 * SROW)
#define FB_BS1   0
#define FB_BS2   512
#define FB_AHI   1024
#define FB_ALO   (FB_AHI + BUFB)
#define FB_B1HI  (FB_ALO + BUFB)
#define FB_B1LO  (FB_B1HI + BUFB)
#define FB_B2HI  (FB_B1LO + BUFB)
#define FB_B2LO  (FB_B2HI + BUFB)
#define FB_QS    FB_B1HI
#define SM_MAX   (FB_B2LO + BUFB)          // 209920 >= both layouts

#if !HAS_TC
__device__ __forceinline__ void gemm3(uint8_t* smem, int aoff, int boff,
                                      float c[2][8][4],
                                      int warp_m, int warp_n, int g, int tg) {
    const int AD = FB_ALO - FB_AHI;
    const int BD = BUFB;
    for (int k0 = 0; k0 < 8; k0++) {
        uint32_t kb = (uint32_t)k0 * 32 + tg * 4;
        uint32_t ah[2][4], al[2][4];
#pragma unroll
        for (int mt = 0; mt < 2; mt++) {
            uint32_t r0 = (uint32_t)aoff + (warp_m * 32 + mt * 16 + g) * SROW + kb;
            uint32_t r1 = r0 + 8 * SROW;
            ah[mt][0] = *(const uint32_t*)(smem + r0);
            ah[mt][1] = *(const uint32_t*)(smem + r1);
            ah[mt][2] = *(const uint32_t*)(smem + r0 + 16);
            ah[mt][3] = *(const uint32_t*)(smem + r1 + 16);
            al[mt][0] = *(const uint32_t*)(smem + r0 + AD);
            al[mt][1] = *(const uint32_t*)(smem + r1 + AD);
            al[mt][2] = *(const uint32_t*)(smem + r0 + AD + 16);
            al[mt][3] = *(const uint32_t*)(smem + r1 + AD + 16);
        }
#pragma unroll
        for (int nt = 0; nt < 8; nt++) {
            uint32_t bo = (uint32_t)boff + (warp_n * 64 + nt * 8 + g) * SROW + kb;
            uint32_t bh0 = *(const uint32_t*)(smem + bo);
            uint32_t bh1 = *(const uint32_t*)(smem + bo + 16);
            uint32_t bl0 = *(const uint32_t*)(smem + bo + BD);
            uint32_t bl1 = *(const uint32_t*)(smem + bo + BD + 16);
#pragma unroll
            for (int mt = 0; mt < 2; mt++) {
                MMA_BF16(c[mt][nt], ah[mt], bh0, bh1);
                MMA_BF16(c[mt][nt], ah[mt], bl0, bl1);
                MMA_BF16(c[mt][nt], al[mt], bh0, bh1);
            }
        }
    }
}
#endif

__global__ void __launch_bounds__(256, 1) __cluster_dims__(1, 1, 1)
mlp_k(int layer, const float* __restrict__ b1, const float* __restrict__ b2) {
    extern __shared__ __align__(1024) uint8_t smem[];
    int tid = threadIdx.x;
    int tile = blockIdx.x;

#if HAS_TC
    uint32_t sb = smem_to_u32(smem);
    int wid = tid >> 5, lane = tid & 31;
    if (wid == 0) { TCGEN05_ALLOC(sb + TC_TMEMPTR, 128); TCGEN05_RELINQ(); }
    if (tid == 0) MBARRIER_INIT(sb + TC_MBAR, 1);

    // cooperative linear loads of pre-swizzled tiles (6 x 32KB)
    {
        const uint4* srcs[6] = {
            g_Ahi + (size_t)tile * 2048, g_Alo + (size_t)tile * 2048,
            g_Bhi + (2 * layer) * 2048, g_Blo + (2 * layer) * 2048,
            g_Bhi + (2 * layer + 1) * 2048, g_Blo + (2 * layer + 1) * 2048};
        const int doffs[6] = {TC_AHI, TC_ALO, TC_B1HI, TC_B1LO, TC_B2HI, TC_B2LO};
#pragma unroll
        for (int a = 0; a < 6; a++) {
            uint4* d = (uint4*)(smem + doffs[a]);
            const uint4* s = srcs[a];
#pragma unroll
            for (int i = 0; i < 8; i++) d[tid + i * 256] = s[tid + i * 256];
        }
        if (tid < 128) ((float*)(smem + TC_BS1))[tid] = b1[tid];
        else           ((float*)(smem + TC_BS2))[tid - 128] = b2[tid - 128];
    }
    FENCE_PROXY_ASYNC();
    __syncthreads();

    uint32_t tmem;
    asm volatile("ld.shared.b32 %0, [%1];" : "=r"(tmem) : "r"(sb + TC_TMEMPTR));

    int r = (wid & 3) * 32 + lane;        // row this thread owns in epilogues
    int hc = (wid >> 2) * 64;             // column half this warp covers

    // ---- MMA1: D = Ahi*B1hi + Ahi*B1lo + Alo*B1hi ----
    if (wid == 0) {
        if (elect_one_pred()) {
            TCGEN05_FENCE_AFTER();
            uint64_t ah = MAKE_SMEM_DESC(sb + TC_AHI), al = MAKE_SMEM_DESC(sb + TC_ALO);
            uint64_t bh = MAKE_SMEM_DESC(sb + TC_B1HI), bl = MAKE_SMEM_DESC(sb + TC_B1LO);
            uint32_t first = 0;
#pragma unroll
            for (int kc = 0; kc < 8; kc++) {
                uint64_t off = (kc < 4) ? (uint64_t)(kc * 2) : (uint64_t)(1024 + (kc - 4) * 2);
                mma_f16_ss(tmem, ah + off, bh + off, MMA_IDESC, first); first = 1;
                mma_f16_ss(tmem, ah + off, bl + off, MMA_IDESC, 1);
                mma_f16_ss(tmem, al + off, bh + off, MMA_IDESC, 1);
            }
            TCGEN05_COMMIT(sb + TC_MBAR);
        }
    }
    MBARRIER_WAIT_PARITY(sb + TC_MBAR, 0);
    TCGEN05_FENCE_AFTER();

    // ---- epilogue1: T = relu(D+b1) -> split bf16 back into A smem tiles ----
    {
        const float* bs1 = (const float*)(smem + TC_BS1);
#pragma unroll
        for (int c0 = hc; c0 < hc + 64; c0 += 32) {
            uint32_t dr[32];
            TCGEN05_LD_X32(dr, tmem + c0);
            TCGEN05_WAIT_LD();
#pragma unroll
            for (int j = 0; j < 32; j += 2) {
                int f = c0 + j;
                float v0 = fmaxf(__uint_as_float(dr[j]) + bs1[f], 0.f);
                float v1 = fmaxf(__uint_as_float(dr[j + 1]) + bs1[f + 1], 0.f);
                float e0, e1;
                unsigned short h0 = bf_hi(v0, e0), h1 = bf_hi(v1, e1);
                uint32_t off = blk_off(r, f);
                *(uint32_t*)(smem + TC_AHI + off) = (uint32_t)h0 | ((uint32_t)h1 << 16);
                *(uint32_t*)(smem + TC_ALO + off) =
                    (uint32_t)bf_rn(e0) | ((uint32_t)bf_rn(e1) << 16);
            }
        }
    }
    TCGEN05_FENCE_BEFORE();
    FENCE_PROXY_ASYNC();
    __syncthreads();

    // ---- MMA2: D = Thi*B2hi + Thi*B2lo + Tlo*B2hi ----
    if (wid == 0) {
        if (elect_one_pred()) {
            TCGEN05_FENCE_AFTER();
            uint64_t ah = MAKE_SMEM_DESC(sb + TC_AHI), al = MAKE_SMEM_DESC(sb + TC_ALO);
            uint64_t bh = MAKE_SMEM_DESC(sb + TC_B2HI), bl = MAKE_SMEM_DESC(sb + TC_B2LO);
            uint32_t first = 0;
#pragma unroll
            for (int kc = 0; kc < 8; kc++) {
                uint64_t off = (kc < 4) ? (uint64_t)(kc * 2) : (uint64_t)(1024 + (kc - 4) * 2);
                mma_f16_ss(tmem, ah + off, bh + off, MMA_IDESC, first); first = 1;
                mma_f16_ss(tmem, ah + off, bl + off, MMA_IDESC, 1);
                mma_f16_ss(tmem, al + off, bh + off, MMA_IDESC, 1);
            }
            TCGEN05_COMMIT(sb + TC_MBAR);
        }
    }
    MBARRIER_WAIT_PARITY(sb + TC_MBAR, 1);
    TCGEN05_FENCE_AFTER();

    // ---- epilogue2: q = relu(D+b2) -> qs smem -> gmem + BN partials ----
    {
        const float* bs2 = (const float*)(smem + TC_BS2);
        float* qs = (float*)(smem + TC_QS);
#pragma unroll
        for (int c0 = hc; c0 < hc + 64; c0 += 32) {
            uint32_t dr[32];
            TCGEN05_LD_X32(dr, tmem + c0);
            TCGEN05_WAIT_LD();
#pragma unroll
            for (int j = 0; j < 32; j++) {
                int f = c0 + j;
                qs[r * 129 + f] = fmaxf(__uint_as_float(dr[j]) + bs2[f], 0.f);
            }
        }
        TCGEN05_FENCE_BEFORE();
        __syncthreads();

        int f = tid & 127, hh = tid >> 7;
        int row0 = tile * 128;
        int valid = min(128, NN - row0);
        int rbeg = hh * 64, rend = min(rbeg + 64, valid);
        float s = 0.f, s2 = 0.f;
        for (int rr = rbeg; rr < rend; rr++) {
            float v = qs[rr * 129 + f];
            s += v; s2 += v * v;
            g_q[(size_t)(row0 + rr) * FF + f] = v;
        }
        atomicAdd(&g_stats[f], s);
        atomicAdd(&g_stats[FF + f], s2);
    }
    __syncthreads();
    if (tid == 0) mbar_inval(sb + TC_MBAR);
    __syncthreads();
    if (wid == 0) TCGEN05_DEALLOC(tmem, 128);

#else  // ---------------- fallback: mma.sync implementation ----------------
    int lane = tid & 31, wid = tid >> 5;
    int g = lane >> 2, tg = lane & 3;
    int warp_m = wid & 3, warp_n = wid >> 2;

    if (tid < 128) ((float*)(smem + FB_BS1))[tid] = b1[tid];
    else           ((float*)(smem + FB_BS2))[tid - 128] = b2[tid - 128];

    {
        const uint4* srcs[6] = {
            g_Ahi + (size_t)tile * 2048, g_Alo + (size_t)tile * 2048,
            g_Bhi + (2 * layer) * 2048, g_Blo + (2 * layer) * 2048,
            g_Bhi + (2 * layer + 1) * 2048, g_Blo + (2 * layer + 1) * 2048};
        const int doffs[6] = {FB_AHI, FB_ALO, FB_B1HI, FB_B1LO, FB_B2HI, FB_B2LO};
#pragma unroll
        for (int a = 0; a < 6; a++) {
            const uint4* s = srcs[a];
            uint8_t* dbase = smem + doffs[a];
#pragma unroll
            for (int i = 0; i < 8; i++) {
                int idx = tid + i * 256;
                int row = idx >> 4, qq = idx & 15;
                *(uint4*)(dbase + row * SROW + qq * 16) = s[idx];
            }
        }
    }
    __syncthreads();

    float c[2][8][4];
#pragma unroll
    for (int mt = 0; mt < 2; mt++)
#pragma unroll
        for (int nt = 0; nt < 8; nt++)
#pragma unroll
            for (int i = 0; i < 4; i++) c[mt][nt][i] = 0.f;

    gemm3(smem, FB_AHI, FB_B1HI, c, warp_m, warp_n, g, tg);
    __syncthreads();

    {
        const float* bs1 = (const float*)(smem + FB_BS1);
#pragma unroll
        for (int mt = 0; mt < 2; mt++) {
            int r0 = warp_m * 32 + mt * 16 + g, r1 = r0 + 8;
#pragma unroll
            for (int nt = 0; nt < 8; nt++) {
                int col = warp_n * 64 + nt * 8 + tg * 2;
                float bc0 = bs1[col], bc1 = bs1[col + 1];
                float v00 = fmaxf(c[mt][nt][0] + bc0, 0.f);
                float v01 = fmaxf(c[mt][nt][1] + bc1, 0.f);
                float v10 = fmaxf(c[mt][nt][2] + bc0, 0.f);
                float v11 = fmaxf(c[mt][nt][3] + bc1, 0.f);
                float e00, e01, e10, e11;
                unsigned short h00 = bf_hi(v00, e00), h01 = bf_hi(v01, e01);
                unsigned short h10 = bf_hi(v10, e10), h11 = bf_hi(v11, e11);
                uint32_t o0 = r0 * SROW + col * 2, o1 = r1 * SROW + col * 2;
                *(uint32_t*)(smem + FB_AHI + o0) = (uint32_t)h00 | ((uint32_t)h01 << 16);
                *(uint32_t*)(smem + FB_AHI + o1) = (uint32_t)h10 | ((uint32_t)h11 << 16);
                *(uint32_t*)(smem + FB_ALO + o0) =
                    (uint32_t)bf_rn(e00) | ((uint32_t)bf_rn(e01) << 16);
                *(uint32_t*)(smem + FB_ALO + o1) =
                    (uint32_t)bf_rn(e10) | ((uint32_t)bf_rn(e11) << 16);
            }
        }
    }
    __syncthreads();

#pragma unroll
    for (int mt = 0; mt < 2; mt++)
#pragma unroll
        for (int nt = 0; nt < 8; nt++)
#pragma unroll
            for (int i = 0; i < 4; i++) c[mt][nt][i] = 0.f;

    gemm3(smem, FB_AHI, FB_B2HI, c, warp_m, warp_n, g, tg);

    {
        const float* bs2 = (const float*)(smem + FB_BS2);
        float* qs = (float*)(smem + FB_QS);
#pragma unroll
        for (int mt = 0; mt < 2; mt++) {
            int r0 = warp_m * 32 + mt * 16 + g, r1 = r0 + 8;
#pragma unroll
            for (int nt = 0; nt < 8; nt++) {
                int col = warp_n * 64 + nt * 8 + tg * 2;
                float bc0 = bs2[col], bc1 = bs2[col + 1];
                qs[r0 * 129 + col]     = fmaxf(c[mt][nt][0] + bc0, 0.f);
                qs[r0 * 129 + col + 1] = fmaxf(c[mt][nt][1] + bc1, 0.f);
                qs[r1 * 129 + col]     = fmaxf(c[mt][nt][2] + bc0, 0.f);
                qs[r1 * 129 + col + 1] = fmaxf(c[mt][nt][3] + bc1, 0.f);
            }
        }
    }
    __syncthreads();

    {
        const float* qs = (const float*)(smem + FB_QS);
        int f = tid & 127, hh = tid >> 7;
        int row0 = tile * 128;
        int valid = min(128, NN - row0);
        int rbeg = hh * 64, rend = min(rbeg + 64, valid);
        float s = 0.f, s2 = 0.f;
        for (int rr = rbeg; rr < rend; rr++) {
            float v = qs[rr * 129 + f];
            s += v; s2 += v * v;
            g_q[(size_t)(row0 + rr) * FF + f] = v;
        }
        atomicAdd(&g_stats[f], s);
        atomicAdd(&g_stats[FF + f], s2);
    }
#endif
}

// ---------------- BatchNorm finalize ---------------------------------------
__global__ void bn_prep_k(const float* __restrict__ gamma, const float* __restrict__ beta) {
    int f = threadIdx.x;
    float inv = 1.0f / (float)NN;
    float mean = g_stats[f] * inv;
    float var = g_stats[FF + f] * inv - mean * mean;
    float sc = rsqrtf(var + BN_EPS) * gamma[f];
    g_sc[f] = sc;
    g_sh[f] = beta[f] - mean * sc;
}

// -------- per-graph add pool, fused BN affine, 2-way row split -------------
__global__ void pool_k(const float* __restrict__ z, const int* __restrict__ batch,
                       float* __restrict__ out, int colOff) {
    __shared__ int bnds[2];
    __shared__ float part[FF];
    int g = blockIdx.x;
    int tid = threadIdx.x;
    if (tid < 2) {
        int v = g + tid;
        int lo = 0, hi = NN;
        while (lo < hi) {
            int m = (lo + hi) >> 1;
            if (batch[m] < v) lo = m + 1; else hi = m;
        }
        bnds[tid] = lo;
    }
    __syncthreads();
    int f = tid & 127, half = tid >> 7;
    int lo = bnds[0], hi = bnds[1];
    float s = 0.f;
    for (int n = lo + half; n < hi; n += 2) s += z[(size_t)n * FF + f];
    if (half) part[f] = s;
    __syncthreads();
    if (!half) {
        float tot = s + part[f];
        float cnt = (float)(hi - lo);
        out[g * (LL * FF) + colOff + f] = fmaf(g_sc[f], tot, cnt * g_sh[f]);
    }
}

// ---------------- host launch ---------------------------------------------
extern "C" void kernel_launch(void* const* d_in, const int* in_sizes, int n_in,
                              void* d_out, int out_size) {
    const float* x     = (const float*)d_in[0];
    const int*   ei    = (const int*)d_in[1];
    const int*   batch = (const int*)d_in[2];
    const float* W1    = (const float*)d_in[3];
    const float* b1    = (const float*)d_in[4];
    const float* W2    = (const float*)d_in[5];
    const float* b2    = (const float*)d_in[6];
    const float* gamma = (const float*)d_in[7];
    const float* beta  = (const float*)d_in[8];
    float* out = (float*)d_out;
    const int* src = ei;
    const int* dst = ei + EE;

    void *pQ, *pDeg, *pStats;
    cudaGetSymbolAddress(&pQ, g_q);
    cudaGetSymbolAddress(&pDeg, g_deg);
    cudaGetSymbolAddress(&pStats, g_stats);
    float* q = (float*)pQ;

    cudaFuncSetAttribute(mlp_k, cudaFuncAttributeMaxDynamicSharedMemorySize, SM_MAX);

    prep_w<<<6, 128>>>(W1, W2);
    cudaMemsetAsync(pDeg, 0, NN * sizeof(int), 0);
    hist_k<<<(EE + 1023) / 1024, 256>>>(dst);
    scan_k<<<1, 1024>>>();
    scatter_k<<<(EE + 1023) / 1024, 256>>>(src, dst);

    for (int i = 0; i < LL; i++) {
        agg_k<<<NN / 8, 256>>>(i == 0 ? x : q, i > 0 ? 1 : 0);
        cudaMemsetAsync(pStats, 0, 2 * FF * sizeof(float), 0);
        mlp_k<<<TILES, 256, SM_MAX>>>(i, b1 + i * FF, b2 + i * FF);
        bn_prep_k<<<1, 128>>>(gamma + i * FF, beta + i * FF);
        pool_k<<<NG, 256>>>(q, batch, out, i * FF);
    }
}

// round 15
// speedup vs baseline: 1.5281x; 1.5281x over previous
#include <cuda_runtime.h>
#include <cuda_bf16.h>
#include <cstdint>

#define NN 100000
#define EE 1600000
#define FF 128
#define NG 512
#define LL 3
#define BN_EPS 1e-5f
#define TILES 782              // ceil(NN/128)

#if defined(__CUDA_ARCH__) && defined(__CUDA_ARCH_FEAT_SM103_ALL)
#define HAS_TC 1
#else
#define HAS_TC 0
#endif

// ---------------- scratch (device globals; no allocation allowed) ----------
__device__ float g_q[NN * FF];
__device__ int   g_deg[NN];
__device__ int   g_off[NN + 1];
__device__ int   g_cur[NN];
__device__ int   g_srcs[EE];
__device__ float g_stats[2 * FF];
__device__ float g_sc[FF];
__device__ float g_sh[FF];
// Split-bf16 activations, 32KB per 128-row tile.
//  - tcgen05 path: blocked-atom SW128 (blk_off)   - fallback: row-major
// Tail rows (>= NN) stay zero (zero-init globals, never written).
__device__ uint4 g_Ahi[TILES * 2048];
__device__ uint4 g_Alo[TILES * 2048];
__device__ uint4 g_Bhi[6 * 2048];
__device__ uint4 g_Blo[6 * 2048];

__device__ __forceinline__ uint32_t blk_off(int r, int k) {
    uint32_t b = (uint32_t)(((r >> 3) + (k >> 6) * 16) * 1024 + (r & 7) * 128 + (k & 63) * 2);
    return b ^ ((b >> 3) & 0x70);
}
__device__ __forceinline__ unsigned short bf_hi(float v, float& rem) {
    __nv_bfloat16 h = __float2bfloat16_rn(v);
    rem = v - __bfloat162float(h);
    return __bfloat16_as_ushort(h);
}
__device__ __forceinline__ unsigned short bf_rn(float v) {
    return __bfloat16_as_ushort(__float2bfloat16_rn(v));
}

#if HAS_TC
// ---------------- tcgen05 helpers (sm_103a only) ---------------------------
__device__ __forceinline__ uint32_t elect_one_pred() {
    uint32_t pred;
    asm volatile(
        "{\n\t.reg .pred p;\n\telect.sync _|p, 0xFFFFFFFF;\n\tselp.b32 %0, 1, 0, p;\n\t}"
        : "=r"(pred));
    return pred;
}
#define TCGEN05_ALLOC(sa, n) \
    asm volatile("tcgen05.alloc.cta_group::1.sync.aligned.shared::cta.b32 [%0], %1;" \
                 :: "r"((uint32_t)(sa)), "r"((uint32_t)(n)) : "memory")
#define TCGEN05_DEALLOC(t, n) \
    asm volatile("tcgen05.dealloc.cta_group::1.sync.aligned.b32 %0, %1;" :: "r"(t), "r"(n))
#define TCGEN05_RELINQ() \
    asm volatile("tcgen05.relinquish_alloc_permit.cta_group::1.sync.aligned;")
#define TCGEN05_COMMIT(mb) \
    asm volatile("tcgen05.commit.cta_group::1.mbarrier::arrive::one.shared::cluster.b64 [%0];" \
                 :: "r"((uint32_t)(mb)) : "memory")
#define TCGEN05_WAIT_LD()  asm volatile("tcgen05.wait::ld.sync.aligned;" ::: "memory")
#define TCGEN05_FENCE_BEFORE() asm volatile("tcgen05.fence::before_thread_sync;" ::: "memory")
#define TCGEN05_FENCE_AFTER()  asm volatile("tcgen05.fence::after_thread_sync;" ::: "memory")
#define TCGEN05_LD_X32(r, ta) \
    asm volatile( \
        "tcgen05.ld.sync.aligned.32x32b.x32.b32 " \
        "{%0, %1, %2, %3, %4, %5, %6, %7, " \
        " %8, %9, %10, %11, %12, %13, %14, %15, " \
        " %16, %17, %18, %19, %20, %21, %22, %23, " \
        " %24, %25, %26, %27, %28, %29, %30, %31}, [%32];" \
        : "=r"((r)[0]),  "=r"((r)[1]),  "=r"((r)[2]),  "=r"((r)[3]), \
          "=r"((r)[4]),  "=r"((r)[5]),  "=r"((r)[6]),  "=r"((r)[7]), \
          "=r"((r)[8]),  "=r"((r)[9]),  "=r"((r)[10]), "=r"((r)[11]), \
          "=r"((r)[12]), "=r"((r)[13]), "=r"((r)[14]), "=r"((r)[15]), \
          "=r"((r)[16]), "=r"((r)[17]), "=r"((r)[18]), "=r"((r)[19]), \
          "=r"((r)[20]), "=r"((r)[21]), "=r"((r)[22]), "=r"((r)[23]), \
          "=r"((r)[24]), "=r"((r)[25]), "=r"((r)[26]), "=r"((r)[27]), \
          "=r"((r)[28]), "=r"((r)[29]), "=r"((r)[30]), "=r"((r)[31]) \
        : "r"(ta))

static constexpr uint64_t SMEM_DESC_BASE_SW128 =
    (uint64_t(2) << 61) | (uint64_t(1) << 46) | (uint64_t(64) << 32) | (uint64_t(1) << 16);
#define MAKE_SMEM_DESC(ba) (SMEM_DESC_BASE_SW128 | ((uint64_t)((ba) >> 4) & 0x3FFF))

__device__ __forceinline__ void mma_f16_ss(uint32_t d, uint64_t a, uint64_t b,
                                           uint32_t idesc, uint32_t en) {
    asm volatile(
        "{\n\t.reg .pred p;\n\tsetp.ne.u32 p, %5, 0;\n\t"
        "tcgen05.mma.cta_group::1.kind::f16 [%0], %1, %2, %3, {%4, %4, %4, %4}, p;\n\t}"
        :: "r"(d), "l"(a), "l"(b), "r"(idesc), "r"(0u), "r"(en) : "memory");
}
// idesc: dtype F32, atype/btype BF16, N=128, M=128
#define MMA_IDESC 0x8200490u

__device__ __forceinline__ uint32_t smem_to_u32(const void* p) {
    uint32_t a;
    asm("{ .reg .u64 t; cvta.to.shared.u64 t, %1; cvt.u32.u64 %0, t; }" : "=r"(a) : "l"(p));
    return a;
}
#define MBARRIER_INIT(mb, c) \
    asm volatile("mbarrier.init.shared.b64 [%0], %1;" :: "r"((uint32_t)(mb)), "r"((uint32_t)(c)) : "memory")
__device__ __forceinline__ void mbar_inval(uint32_t mb) {
    asm volatile("mbarrier.inval.shared.b64 [%0];" :: "r"(mb) : "memory");
}
#define MBARRIER_WAIT_PARITY(mb, ph) do {                                      \
    uint32_t _mb = (uint32_t)(mb); uint32_t _p = (uint32_t)(ph); uint32_t _d;  \
    asm volatile("{\n\t.reg .pred p;\n\t"                                      \
        "mbarrier.try_wait.parity.acquire.cta.shared::cta.b64 p, [%1], %2;\n\t"\
        "selp.b32 %0, 1, 0, p;\n\t}" : "=r"(_d) : "r"(_mb), "r"(_p) : "memory");\
    if (!_d) {                                                                 \
        asm volatile("{\n\t.reg .pred P1;\n\t"                                 \
            "WL_%=:\n\t"                                                       \
            "mbarrier.try_wait.parity.acquire.cta.shared::cta.b64 P1, [%0], %1, 0x989680;\n\t" \
            "@P1 bra.uni WD_%=;\n\tbra.uni WL_%=;\n\tWD_%=:\n\t}"              \
            :: "r"(_mb), "r"(_p) : "memory");                                  \
    } } while (0)
#define FENCE_PROXY_ASYNC() asm volatile("fence.proxy.async.shared::cta;" ::: "memory")
#else
#define MMA_BF16(C, A, B0, B1)                                                 \
    asm volatile(                                                              \
        "mma.sync.aligned.m16n8k16.row.col.f32.bf16.bf16.f32 "                 \
        "{%0,%1,%2,%3}, {%4,%5,%6,%7}, {%8,%9}, {%0,%1,%2,%3};"                \
        : "+f"((C)[0]), "+f"((C)[1]), "+f"((C)[2]), "+f"((C)[3])               \
        : "r"((A)[0]), "r"((A)[1]), "r"((A)[2]), "r"((A)[3]),                  \
          "r"(B0), "r"(B1))
#endif

// ---------------- CSR build (R6 exact) --------------------------------------
__global__ void hist_k(const int* __restrict__ dst) {
    int e = blockIdx.x * 256 + threadIdx.x;
    if (e < EE) atomicAdd(&g_deg[dst[e]], 1);
}

__global__ void scan_k() {
    const int T = 1024;
    int tid = threadIdx.x;
    int per = (NN + T - 1) / T;
    int start = min(tid * per, NN), end = min(start + per, NN);
    int s = 0;
    for (int i = start; i < end; i++) s += g_deg[i];
    int lane = tid & 31, w = tid >> 5;
    int v = s;
#pragma unroll
    for (int o = 1; o < 32; o <<= 1) {
        int t = __shfl_up_sync(0xffffffffu, v, o);
        if (lane >= o) v += t;
    }
    __shared__ int wsum[32];
    if (lane == 31) wsum[w] = v;
    __syncthreads();
    if (w == 0) {
        int x = wsum[lane];
#pragma unroll
        for (int o = 1; o < 32; o <<= 1) {
            int t = __shfl_up_sync(0xffffffffu, x, o);
            if (lane >= o) x += t;
        }
        wsum[lane] = x;
    }
    __syncthreads();
    int excl = v - s + (w > 0 ? wsum[w - 1] : 0);
    int run = excl;
    for (int i = start; i < end; i++) {
        int c = g_deg[i];
        g_off[i] = run;
        g_cur[i] = run;
        run += c;
    }
    if (tid == T - 1) g_off[NN] = run;
}

__global__ void scatter_k(const int* __restrict__ src, const int* __restrict__ dst) {
    int e = blockIdx.x * 256 + threadIdx.x;
    if (e < EE) {
        int d = dst[e];
        int p = atomicAdd(&g_cur[d], 1);
        g_srcs[p] = src[e];
    }
}

// ---------------- weight prep: Wt[n][k]=W[k][n], split bf16 ---------------
__global__ void prep_w(const float* __restrict__ W1, const float* __restrict__ W2) {
    int b = blockIdx.x;
    int layer = b >> 1;
    const float* W = ((b & 1) ? W2 : W1) + layer * FF * FF;
    uint8_t* dh = (uint8_t*)g_Bhi + b * 32768;
    uint8_t* dl = (uint8_t*)g_Blo + b * 32768;
    int n = threadIdx.x;
    for (int k = 0; k < FF; k++) {
        float w = W[k * FF + n];
        float rem;
        unsigned short h = bf_hi(w, rem);
        unsigned short l = bf_rn(rem);
#if HAS_TC
        uint32_t off = blk_off(n, k);
#else
        uint32_t off = (uint32_t)(n * 128 + k) * 2;
#endif
        *(unsigned short*)(dh + off) = h;
        *(unsigned short*)(dl + off) = l;
    }
}

// ------ aggregation with fused BN affine (R6 exact) ------------------------
__global__ void agg_k(const float* __restrict__ h, int affine) {
    int gw = (blockIdx.x * blockDim.x + threadIdx.x) >> 5;
    int lane = threadIdx.x & 31;
    if (gw >= NN) return;
    const float4* h4 = (const float4*)h;
    float4 acc = h4[gw * 32 + lane];
    int s0 = g_off[gw], s1 = g_off[gw + 1];
    for (int e = s0; e < s1; e++) {
        int s = g_srcs[e];
        float4 v = __ldg(&h4[s * 32 + lane]);
        acc.x += v.x; acc.y += v.y; acc.z += v.z; acc.w += v.w;
    }
    if (affine) {
        float4 sc4 = ((const float4*)g_sc)[lane];
        float4 sh4 = ((const float4*)g_sh)[lane];
        float cnt = (float)(s1 - s0 + 1);
        acc.x = fmaf(sc4.x, acc.x, cnt * sh4.x);
        acc.y = fmaf(sc4.y, acc.y, cnt * sh4.y);
        acc.z = fmaf(sc4.z, acc.z, cnt * sh4.z);
        acc.w = fmaf(sc4.w, acc.w, cnt * sh4.w);
    }
    float r0, r1, r2, r3;
    unsigned short h0 = bf_hi(acc.x, r0), h1 = bf_hi(acc.y, r1);
    unsigned short h2 = bf_hi(acc.z, r2), h3 = bf_hi(acc.w, r3);
    uint2 hv = make_uint2((uint32_t)h0 | ((uint32_t)h1 << 16),
                          (uint32_t)h2 | ((uint32_t)h3 << 16));
    uint2 lv = make_uint2((uint32_t)bf_rn(r0) | ((uint32_t)bf_rn(r1) << 16),
                          (uint32_t)bf_rn(r2) | ((uint32_t)bf_rn(r3) << 16));
#if HAS_TC
    int tile = gw >> 7, r = gw & 127;
    uint32_t off = blk_off(r, lane * 4);
    *(uint2*)((uint8_t*)g_Ahi + tile * 32768 + off) = hv;
    *(uint2*)((uint8_t*)g_Alo + tile * 32768 + off) = lv;
#else
    ((uint2*)g_Ahi)[gw * 32 + lane] = hv;
    ((uint2*)g_Alo)[gw * 32 + lane] = lv;
#endif
}

// ---------------- fused MLP (R6 body; B2 load overlapped with MMA1) --------
// TC layout:
#define TC_TMEMPTR 0
#define TC_MBAR    8
#define TC_BS1     64
#define TC_BS2     576
#define TC_AHI     2048
#define TC_ALO     (TC_AHI + 32768)
#define TC_B1HI    (TC_ALO + 32768)
#define TC_B1LO    (TC_B1HI + 32768)
#define TC_B2HI    (TC_B1LO + 32768)
#define TC_B2LO    (TC_B2HI + 32768)
#define TC_QS      TC_AHI                  // reuse after MMA2 (needs 66048B <= A+B1 region)
#define TC_TOTAL   (TC_B2LO + 32768)       // 198656
// fallback layout: rows padded to 272B
#define SROW 272
#define BUFB (128 * SROW)
#define FB_BS1   0
#define FB_BS2   512
#define FB_AHI   1024
#define FB_ALO   (FB_AHI + BUFB)
#define FB_B1HI  (FB_ALO + BUFB)
#define FB_B1LO  (FB_B1HI + BUFB)
#define FB_B2HI  (FB_B1LO + BUFB)
#define FB_B2LO  (FB_B2HI + BUFB)
#define FB_QS    FB_B1HI
#define SM_MAX   (FB_B2LO + BUFB)          // 209920 >= both layouts

#if !HAS_TC
__device__ __forceinline__ void gemm3(uint8_t* smem, int aoff, int boff,
                                      float c[2][8][4],
                                      int warp_m, int warp_n, int g, int tg) {
    const int AD = FB_ALO - FB_AHI;
    const int BD = BUFB;
    for (int k0 = 0; k0 < 8; k0++) {
        uint32_t kb = (uint32_t)k0 * 32 + tg * 4;
        uint32_t ah[2][4], al[2][4];
#pragma unroll
        for (int mt = 0; mt < 2; mt++) {
            uint32_t r0 = (uint32_t)aoff + (warp_m * 32 + mt * 16 + g) * SROW + kb;
            uint32_t r1 = r0 + 8 * SROW;
            ah[mt][0] = *(const uint32_t*)(smem + r0);
            ah[mt][1] = *(const uint32_t*)(smem + r1);
            ah[mt][2] = *(const uint32_t*)(smem + r0 + 16);
            ah[mt][3] = *(const uint32_t*)(smem + r1 + 16);
            al[mt][0] = *(const uint32_t*)(smem + r0 + AD);
            al[mt][1] = *(const uint32_t*)(smem + r1 + AD);
            al[mt][2] = *(const uint32_t*)(smem + r0 + AD + 16);
            al[mt][3] = *(const uint32_t*)(smem + r1 + AD + 16);
        }
#pragma unroll
        for (int nt = 0; nt < 8; nt++) {
            uint32_t bo = (uint32_t)boff + (warp_n * 64 + nt * 8 + g) * SROW + kb;
            uint32_t bh0 = *(const uint32_t*)(smem + bo);
            uint32_t bh1 = *(const uint32_t*)(smem + bo + 16);
            uint32_t bl0 = *(const uint32_t*)(smem + bo + BD);
            uint32_t bl1 = *(const uint32_t*)(smem + bo + BD + 16);
#pragma unroll
            for (int mt = 0; mt < 2; mt++) {
                MMA_BF16(c[mt][nt], ah[mt], bh0, bh1);
                MMA_BF16(c[mt][nt], ah[mt], bl0, bl1);
                MMA_BF16(c[mt][nt], al[mt], bh0, bh1);
            }
        }
    }
}
#endif

__global__ void __launch_bounds__(256, 1) __cluster_dims__(1, 1, 1)
mlp_k(int layer, const float* __restrict__ b1, const float* __restrict__ b2) {
    extern __shared__ __align__(1024) uint8_t smem[];
    int tid = threadIdx.x;
    int tile = blockIdx.x;

#if HAS_TC
    uint32_t sb = smem_to_u32(smem);
    int wid = tid >> 5, lane = tid & 31;
    if (wid == 0) { TCGEN05_ALLOC(sb + TC_TMEMPTR, 128); TCGEN05_RELINQ(); }
    if (tid == 0) MBARRIER_INIT(sb + TC_MBAR, 1);

    // phase 1 loads: A hi/lo + B1 hi/lo (MMA1 operands) + biases
    {
        const uint4* srcs[4] = {
            g_Ahi + (size_t)tile * 2048, g_Alo + (size_t)tile * 2048,
            g_Bhi + (2 * layer) * 2048, g_Blo + (2 * layer) * 2048};
        const int doffs[4] = {TC_AHI, TC_ALO, TC_B1HI, TC_B1LO};
#pragma unroll
        for (int a = 0; a < 4; a++) {
            uint4* d = (uint4*)(smem + doffs[a]);
            const uint4* s = srcs[a];
#pragma unroll
            for (int i = 0; i < 8; i++) d[tid + i * 256] = s[tid + i * 256];
        }
        if (tid < 128) ((float*)(smem + TC_BS1))[tid] = b1[tid];
        else           ((float*)(smem + TC_BS2))[tid - 128] = b2[tid - 128];
    }
    FENCE_PROXY_ASYNC();
    __syncthreads();

    uint32_t tmem;
    asm volatile("ld.shared.b32 %0, [%1];" : "=r"(tmem) : "r"(sb + TC_TMEMPTR));

    int r = (wid & 3) * 32 + lane;        // row this thread owns in epilogues
    int hc = (wid >> 2) * 64;             // column half this warp covers

    // ---- MMA1: D = Ahi*B1hi + Ahi*B1lo + Alo*B1hi ----
    if (wid == 0) {
        if (elect_one_pred()) {
            TCGEN05_FENCE_AFTER();
            uint64_t ah = MAKE_SMEM_DESC(sb + TC_AHI), al = MAKE_SMEM_DESC(sb + TC_ALO);
            uint64_t bh = MAKE_SMEM_DESC(sb + TC_B1HI), bl = MAKE_SMEM_DESC(sb + TC_B1LO);
            uint32_t first = 0;
#pragma unroll
            for (int kc = 0; kc < 8; kc++) {
                uint64_t off = (kc < 4) ? (uint64_t)(kc * 2) : (uint64_t)(1024 + (kc - 4) * 2);
                mma_f16_ss(tmem, ah + off, bh + off, MMA_IDESC, first); first = 1;
                mma_f16_ss(tmem, ah + off, bl + off, MMA_IDESC, 1);
                mma_f16_ss(tmem, al + off, bh + off, MMA_IDESC, 1);
            }
            TCGEN05_COMMIT(sb + TC_MBAR);
        }
    }

    // ---- phase 2 loads: B2 hi/lo, overlapped with MMA1 execution ----
    {
        const uint4* s2[2] = {g_Bhi + (2 * layer + 1) * 2048, g_Blo + (2 * layer + 1) * 2048};
        const int d2[2] = {TC_B2HI, TC_B2LO};
#pragma unroll
        for (int a = 0; a < 2; a++) {
            uint4* d = (uint4*)(smem + d2[a]);
            const uint4* s = s2[a];
#pragma unroll
            for (int i = 0; i < 8; i++) d[tid + i * 256] = s[tid + i * 256];
        }
    }

    MBARRIER_WAIT_PARITY(sb + TC_MBAR, 0);
    TCGEN05_FENCE_AFTER();

    // ---- epilogue1: T = relu(D+b1) -> split bf16 back into A smem tiles ----
    {
        const float* bs1 = (const float*)(smem + TC_BS1);
#pragma unroll
        for (int c0 = hc; c0 < hc + 64; c0 += 32) {
            uint32_t dr[32];
            TCGEN05_LD_X32(dr, tmem + c0);
            TCGEN05_WAIT_LD();
#pragma unroll
            for (int j = 0; j < 32; j += 2) {
                int f = c0 + j;
                float v0 = fmaxf(__uint_as_float(dr[j]) + bs1[f], 0.f);
                float v1 = fmaxf(__uint_as_float(dr[j + 1]) + bs1[f + 1], 0.f);
                float e0, e1;
                unsigned short h0 = bf_hi(v0, e0), h1 = bf_hi(v1, e1);
                uint32_t off = blk_off(r, f);
                *(uint32_t*)(smem + TC_AHI + off) = (uint32_t)h0 | ((uint32_t)h1 << 16);
                *(uint32_t*)(smem + TC_ALO + off) =
                    (uint32_t)bf_rn(e0) | ((uint32_t)bf_rn(e1) << 16);
            }
        }
    }
    TCGEN05_FENCE_BEFORE();
    FENCE_PROXY_ASYNC();
    __syncthreads();

    // ---- MMA2: D = Thi*B2hi + Thi*B2lo + Tlo*B2hi ----
    if (wid == 0) {
        if (elect_one_pred()) {
            TCGEN05_FENCE_AFTER();
            uint64_t ah = MAKE_SMEM_DESC(sb + TC_AHI), al = MAKE_SMEM_DESC(sb + TC_ALO);
            uint64_t bh = MAKE_SMEM_DESC(sb + TC_B2HI), bl = MAKE_SMEM_DESC(sb + TC_B2LO);
            uint32_t first = 0;
#pragma unroll
            for (int kc = 0; kc < 8; kc++) {
                uint64_t off = (kc < 4) ? (uint64_t)(kc * 2) : (uint64_t)(1024 + (kc - 4) * 2);
                mma_f16_ss(tmem, ah + off, bh + off, MMA_IDESC, first); first = 1;
                mma_f16_ss(tmem, ah + off, bl + off, MMA_IDESC, 1);
                mma_f16_ss(tmem, al + off, bh + off, MMA_IDESC, 1);
            }
            TCGEN05_COMMIT(sb + TC_MBAR);
        }
    }
    MBARRIER_WAIT_PARITY(sb + TC_MBAR, 1);
    TCGEN05_FENCE_AFTER();

    // ---- epilogue2: q = relu(D+b2) -> qs smem -> gmem + BN partials ----
    {
        const float* bs2 = (const float*)(smem + TC_BS2);
        float* qs = (float*)(smem + TC_QS);
#pragma unroll
        for (int c0 = hc; c0 < hc + 64; c0 += 32) {
            uint32_t dr[32];
            TCGEN05_LD_X32(dr, tmem + c0);
            TCGEN05_WAIT_LD();
#pragma unroll
            for (int j = 0; j < 32; j++) {
                int f = c0 + j;
                qs[r * 129 + f] = fmaxf(__uint_as_float(dr[j]) + bs2[f], 0.f);
            }
        }
        TCGEN05_FENCE_BEFORE();
        __syncthreads();

        int f = tid & 127, hh = tid >> 7;
        int row0 = tile * 128;
        int valid = min(128, NN - row0);
        int rbeg = hh * 64, rend = min(rbeg + 64, valid);
        float s = 0.f, s2 = 0.f;
        for (int rr = rbeg; rr < rend; rr++) {
            float v = qs[rr * 129 + f];
            s += v; s2 += v * v;
            g_q[(size_t)(row0 + rr) * FF + f] = v;
        }
        atomicAdd(&g_stats[f], s);
        atomicAdd(&g_stats[FF + f], s2);
    }
    __syncthreads();
    if (tid == 0) mbar_inval(sb + TC_MBAR);
    __syncthreads();
    if (wid == 0) TCGEN05_DEALLOC(tmem, 128);

#else  // ---------------- fallback: mma.sync implementation (R6 exact) -----
    int lane = tid & 31, wid = tid >> 5;
    int g = lane >> 2, tg = lane & 3;
    int warp_m = wid & 3, warp_n = wid >> 2;

    if (tid < 128) ((float*)(smem + FB_BS1))[tid] = b1[tid];
    else           ((float*)(smem + FB_BS2))[tid - 128] = b2[tid - 128];

    {
        const uint4* srcs[6] = {
            g_Ahi + (size_t)tile * 2048, g_Alo + (size_t)tile * 2048,
            g_Bhi + (2 * layer) * 2048, g_Blo + (2 * layer) * 2048,
            g_Bhi + (2 * layer + 1) * 2048, g_Blo + (2 * layer + 1) * 2048};
        const int doffs[6] = {FB_AHI, FB_ALO, FB_B1HI, FB_B1LO, FB_B2HI, FB_B2LO};
#pragma unroll
        for (int a = 0; a < 6; a++) {
            const uint4* s = srcs[a];
            uint8_t* dbase = smem + doffs[a];
#pragma unroll
            for (int i = 0; i < 8; i++) {
                int idx = tid + i * 256;
                int row = idx >> 4, qq = idx & 15;
                *(uint4*)(dbase + row * SROW + qq * 16) = s[idx];
            }
        }
    }
    __syncthreads();

    float c[2][8][4];
#pragma unroll
    for (int mt = 0; mt < 2; mt++)
#pragma unroll
        for (int nt = 0; nt < 8; nt++)
#pragma unroll
            for (int i = 0; i < 4; i++) c[mt][nt][i] = 0.f;

    gemm3(smem, FB_AHI, FB_B1HI, c, warp_m, warp_n, g, tg);
    __syncthreads();

    {
        const float* bs1 = (const float*)(smem + FB_BS1);
#pragma unroll
        for (int mt = 0; mt < 2; mt++) {
            int r0 = warp_m * 32 + mt * 16 + g, r1 = r0 + 8;
#pragma unroll
            for (int nt = 0; nt < 8; nt++) {
                int col = warp_n * 64 + nt * 8 + tg * 2;
                float bc0 = bs1[col], bc1 = bs1[col + 1];
                float v00 = fmaxf(c[mt][nt][0] + bc0, 0.f);
                float v01 = fmaxf(c[mt][nt][1] + bc1, 0.f);
                float v10 = fmaxf(c[mt][nt][2] + bc0, 0.f);
                float v11 = fmaxf(c[mt][nt][3] + bc1, 0.f);
                float e00, e01, e10, e11;
                unsigned short h00 = bf_hi(v00, e00), h01 = bf_hi(v01, e01);
                unsigned short h10 = bf_hi(v10, e10), h11 = bf_hi(v11, e11);
                uint32_t o0 = r0 * SROW + col * 2, o1 = r1 * SROW + col * 2;
                *(uint32_t*)(smem + FB_AHI + o0) = (uint32_t)h00 | ((uint32_t)h01 << 16);
                *(uint32_t*)(smem + FB_AHI + o1) = (uint32_t)h10 | ((uint32_t)h11 << 16);
                *(uint32_t*)(smem + FB_ALO + o0) =
                    (uint32_t)bf_rn(e00) | ((uint32_t)bf_rn(e01) << 16);
                *(uint32_t*)(smem + FB_ALO + o1) =
                    (uint32_t)bf_rn(e10) | ((uint32_t)bf_rn(e11) << 16);
            }
        }
    }
    __syncthreads();

#pragma unroll
    for (int mt = 0; mt < 2; mt++)
#pragma unroll
        for (int nt = 0; nt < 8; nt++)
#pragma unroll
            for (int i = 0; i < 4; i++) c[mt][nt][i] = 0.f;

    gemm3(smem, FB_AHI, FB_B2HI, c, warp_m, warp_n, g, tg);

    {
        const float* bs2 = (const float*)(smem + FB_BS2);
        float* qs = (float*)(smem + FB_QS);
#pragma unroll
        for (int mt = 0; mt < 2; mt++) {
            int r0 = warp_m * 32 + mt * 16 + g, r1 = r0 + 8;
#pragma unroll
            for (int nt = 0; nt < 8; nt++) {
                int col = warp_n * 64 + nt * 8 + tg * 2;
                float bc0 = bs2[col], bc1 = bs2[col + 1];
                qs[r0 * 129 + col]     = fmaxf(c[mt][nt][0] + bc0, 0.f);
                qs[r0 * 129 + col + 1] = fmaxf(c[mt][nt][1] + bc1, 0.f);
                qs[r1 * 129 + col]     = fmaxf(c[mt][nt][2] + bc0, 0.f);
                qs[r1 * 129 + col + 1] = fmaxf(c[mt][nt][3] + bc1, 0.f);
            }
        }
    }
    __syncthreads();

    {
        const float* qs = (const float*)(smem + FB_QS);
        int f = tid & 127, hh = tid >> 7;
        int row0 = tile * 128;
        int valid = min(128, NN - row0);
        int rbeg = hh * 64, rend = min(rbeg + 64, valid);
        float s = 0.f, s2 = 0.f;
        for (int rr = rbeg; rr < rend; rr++) {
            float v = qs[rr * 129 + f];
            s += v; s2 += v * v;
            g_q[(size_t)(row0 + rr) * FF + f] = v;
        }
        atomicAdd(&g_stats[f], s);
        atomicAdd(&g_stats[FF + f], s2);
    }
#endif
}

// ---------------- BatchNorm finalize ---------------------------------------
__global__ void bn_prep_k(const float* __restrict__ gamma, const float* __restrict__ beta) {
    int f = threadIdx.x;
    float inv = 1.0f / (float)NN;
    float mean = g_stats[f] * inv;
    float var = g_stats[FF + f] * inv - mean * mean;
    float sc = rsqrtf(var + BN_EPS) * gamma[f];
    g_sc[f] = sc;
    g_sh[f] = beta[f] - mean * sc;
}

// -------- per-graph add pool, fused BN affine, 2-way row split (R10-verified)
__global__ void pool_k(const float* __restrict__ z, const int* __restrict__ batch,
                       float* __restrict__ out, int colOff) {
    __shared__ int bnds[2];
    __shared__ float part[FF];
    int g = blockIdx.x;
    int tid = threadIdx.x;
    if (tid < 2) {
        int v = g + tid;
        int lo = 0, hi = NN;
        while (lo < hi) {
            int m = (lo + hi) >> 1;
            if (batch[m] < v) lo = m + 1; else hi = m;
        }
        bnds[tid] = lo;
    }
    __syncthreads();
    int f = tid & 127, half = tid >> 7;
    int lo = bnds[0], hi = bnds[1];
    float s = 0.f;
    for (int n = lo + half; n < hi; n += 2) s += z[(size_t)n * FF + f];
    if (half) part[f] = s;
    __syncthreads();
    if (!half) {
        float tot = s + part[f];
        float cnt = (float)(hi - lo);
        out[g * (LL * FF) + colOff + f] = fmaf(g_sc[f], tot, cnt * g_sh[f]);
    }
}

// ---------------- host launch ---------------------------------------------
extern "C" void kernel_launch(void* const* d_in, const int* in_sizes, int n_in,
                              void* d_out, int out_size) {
    const float* x     = (const float*)d_in[0];
    const int*   ei    = (const int*)d_in[1];
    const int*   batch = (const int*)d_in[2];
    const float* W1    = (const float*)d_in[3];
    const float* b1    = (const float*)d_in[4];
    const float* W2    = (const float*)d_in[5];
    const float* b2    = (const float*)d_in[6];
    const float* gamma = (const float*)d_in[7];
    const float* beta  = (const float*)d_in[8];
    float* out = (float*)d_out;
    const int* src = ei;
    const int* dst = ei + EE;

    void *pQ, *pDeg, *pStats;
    cudaGetSymbolAddress(&pQ, g_q);
    cudaGetSymbolAddress(&pDeg, g_deg);
    cudaGetSymbolAddress(&pStats, g_stats);
    float* q = (float*)pQ;

    cudaFuncSetAttribute(mlp_k, cudaFuncAttributeMaxDynamicSharedMemorySize, SM_MAX);

    prep_w<<<6, 128>>>(W1, W2);
    cudaMemsetAsync(pDeg, 0, NN * sizeof(int), 0);
    hist_k<<<EE / 256, 256>>>(dst);
    scan_k<<<1, 1024>>>();
    scatter_k<<<EE / 256, 256>>>(src, dst);

    for (int i = 0; i < LL; i++) {
        agg_k<<<NN / 8, 256>>>(i == 0 ? x : q, i > 0 ? 1 : 0);
        cudaMemsetAsync(pStats, 0, 2 * FF * sizeof(float), 0);
        mlp_k<<<TILES, 256, SM_MAX>>>(i, b1 + i * FF, b2 + i * FF);
        bn_prep_k<<<1, 128>>>(gamma + i * FF, beta + i * FF);
        pool_k<<<NG, 256>>>(q, batch, out, i * FF);
    }
}